// round 3
// baseline (speedup 1.0000x reference)
#include <cuda_runtime.h>
#include <cuda_bf16.h>
#include <cstdint>

// ---------------------------------------------------------------------------
// Problem constants
// ---------------------------------------------------------------------------
#define L_Q   64
#define KEY_N 65
#define H_N   8
#define HD_N  64
#define C_N   512
#define NB_N  1024              // B * nb = 2 * 512
#define MQ_N  (NB_N * L_Q)      // 65536 rows of x / q / attn-out
#define MKV_N (NB_N * KEY_N)    // 66560 rows of kv

// ---------------------------------------------------------------------------
// Device scratch (no cudaMalloc allowed)
// ---------------------------------------------------------------------------
__device__ __nv_bfloat16 g_xh[MQ_N * C_N];          // 67 MB  x hi
__device__ __nv_bfloat16 g_xl[MQ_N * C_N];          // 67 MB  x lo
__device__ __nv_bfloat16 g_bmh[NB_N * C_N];         // 1 MB   block mean hi
__device__ __nv_bfloat16 g_bml[NB_N * C_N];         // 1 MB   block mean lo
__device__ __nv_bfloat16 g_wqkvh[3 * C_N * C_N];    // 1.5 MB qkv_w hi
__device__ __nv_bfloat16 g_wqkvl[3 * C_N * C_N];    // 1.5 MB qkv_w lo
__device__ __nv_bfloat16 g_wph[C_N * C_N];          // 0.5 MB proj_w hi
__device__ __nv_bfloat16 g_wpl[C_N * C_N];          // 0.5 MB proj_w lo
__device__ __nv_bfloat16 g_ath[MQ_N * C_N];         // 67 MB  attn-out hi
__device__ __nv_bfloat16 g_atl[MQ_N * C_N];         // 67 MB  attn-out lo
__device__ float g_q[MQ_N * C_N];                   // 134 MB q (fp32)
__device__ float g_kv[MKV_N * 2 * C_N];             // 272 MB [k|v] (fp32)

// ---------------------------------------------------------------------------
// Helpers
// ---------------------------------------------------------------------------
__device__ __forceinline__ void split2(float f, __nv_bfloat16& h, __nv_bfloat16& l)
{
    h = __float2bfloat16(f);
    l = __float2bfloat16(f - __bfloat162float(h));
}

__device__ __forceinline__ void mma_bf16(float* c, const uint32_t* a, const uint32_t* b)
{
    asm volatile(
        "mma.sync.aligned.m16n8k16.row.col.f32.bf16.bf16.f32 "
        "{%0,%1,%2,%3}, {%4,%5,%6,%7}, {%8,%9}, {%0,%1,%2,%3};\n"
        : "+f"(c[0]), "+f"(c[1]), "+f"(c[2]), "+f"(c[3])
        : "r"(a[0]), "r"(a[1]), "r"(a[2]), "r"(a[3]),
          "r"(b[0]), "r"(b[1]));
}

// ---------------------------------------------------------------------------
// Kernel 0: fp32 -> bf16 hi/lo split (processes 4 floats / thread)
// ---------------------------------------------------------------------------
__global__ void split_kernel(const float* __restrict__ src,
                             __nv_bfloat16* __restrict__ hi,
                             __nv_bfloat16* __restrict__ lo, int n4)
{
    int i = blockIdx.x * 256 + threadIdx.x;
    if (i >= n4) return;
    float4 f = reinterpret_cast<const float4*>(src)[i];
    __nv_bfloat16 h0, h1, h2, h3, l0, l1, l2, l3;
    split2(f.x, h0, l0); split2(f.y, h1, l1);
    split2(f.z, h2, l2); split2(f.w, h3, l3);
    __nv_bfloat162 ha; ha.x = h0; ha.y = h1;
    __nv_bfloat162 hb; hb.x = h2; hb.y = h3;
    __nv_bfloat162 la; la.x = l0; la.y = l1;
    __nv_bfloat162 lb; lb.x = l2; lb.y = l3;
    __nv_bfloat162* hp = reinterpret_cast<__nv_bfloat162*>(hi) + (size_t)i * 2;
    __nv_bfloat162* lp = reinterpret_cast<__nv_bfloat162*>(lo) + (size_t)i * 2;
    hp[0] = ha; hp[1] = hb;
    lp[0] = la; lp[1] = lb;
}

// ---------------------------------------------------------------------------
// Kernel 1: per-block mean of x over 64 tokens -> bf16 hi/lo
// ---------------------------------------------------------------------------
__global__ void mean_kernel(const float* __restrict__ x)
{
    int bb = blockIdx.x;         // 0..1023
    int c  = threadIdx.x;        // 0..511
    const float* xp = x + ((size_t)bb * L_Q) * C_N + c;
    float s = 0.f;
#pragma unroll 8
    for (int l = 0; l < L_Q; ++l) s += xp[(size_t)l * C_N];
    s *= (1.0f / 64.0f);
    __nv_bfloat16 h, l;
    split2(s, h, l);
    g_bmh[bb * C_N + c] = h;
    g_bml[bb * C_N + c] = l;
}

// ---------------------------------------------------------------------------
// Kernel 2: bf16 split-precision GEMM  out[M,N] = A[M,512] @ W[N,512]^T + b
//   3-product scheme: Ah*Wh + Ah*Wl + Al*Wh  (fp32 accumulate)
//   CTA tile 128(M) x 64(N), BK=32, 256 threads, warp tile 32x32.
//   kvmode=1: logical A row r -> bb=r/65, l=r%65; l<64 -> x row, l==64 -> mean.
// ---------------------------------------------------------------------------
#define PADW 20   // 32-bit words per smem row (16 used) -> conflict-free frags

__global__ __launch_bounds__(256)
void gemm_bf16(const __nv_bfloat16* __restrict__ Ah,
               const __nv_bfloat16* __restrict__ Al,
               const __nv_bfloat16* __restrict__ Wh,
               const __nv_bfloat16* __restrict__ Wl,
               const float* __restrict__ bias,
               float* __restrict__ out,
               int ldo, int kvmode)
{
    __shared__ uint32_t sAh[128 * PADW];
    __shared__ uint32_t sAl[128 * PADW];
    __shared__ uint32_t sWh[64 * PADW];
    __shared__ uint32_t sWl[64 * PADW];

    const int tid = threadIdx.x;
    const int m0 = blockIdx.x * 128;
    const int n0 = blockIdx.y * 64;

    // ---- global load mapping ----
    const int ar  = tid >> 1;            // A row 0..127 (2 threads / row)
    const int awo = (tid & 1) * 8;       // word offset 0 or 8 (8 words each)
    const __nv_bfloat16 *arow_h, *arow_l;
    if (!kvmode) {
        arow_h = Ah + (size_t)(m0 + ar) * C_N;
        arow_l = Al + (size_t)(m0 + ar) * C_N;
    } else {
        int rg = m0 + ar;
        int bb = rg / KEY_N;
        int l  = rg - bb * KEY_N;
        if (l < L_Q) {
            arow_h = Ah + (size_t)(bb * L_Q + l) * C_N;
            arow_l = Al + (size_t)(bb * L_Q + l) * C_N;
        } else {
            arow_h = g_bmh + (size_t)bb * C_N;
            arow_l = g_bml + (size_t)bb * C_N;
        }
    }
    const int wr  = tid >> 2;            // W row 0..63 (4 threads / row)
    const int wwo = (tid & 3) * 4;       // word offset 0,4,8,12
    const __nv_bfloat16* wrow_h = Wh + (size_t)(n0 + wr) * C_N;
    const __nv_bfloat16* wrow_l = Wl + (size_t)(n0 + wr) * C_N;

    // ---- compute mapping ----
    const int lane = tid & 31, warp = tid >> 5;
    const int g = lane >> 2, tig = lane & 3;
    const int mb = (warp >> 1) * 32;     // warp M offset (0,32,64,96)
    const int nb = (warp & 1) * 32;      // warp N offset (0,32)

    float acc[2][4][4] = {};

    // ---- prologue prefetch (k0 = 0) ----
    uint4 pa_h0 = reinterpret_cast<const uint4*>(arow_h)[(awo >> 2) + 0];
    uint4 pa_h1 = reinterpret_cast<const uint4*>(arow_h)[(awo >> 2) + 1];
    uint4 pa_l0 = reinterpret_cast<const uint4*>(arow_l)[(awo >> 2) + 0];
    uint4 pa_l1 = reinterpret_cast<const uint4*>(arow_l)[(awo >> 2) + 1];
    uint4 pw_h  = reinterpret_cast<const uint4*>(wrow_h)[tid & 3];
    uint4 pw_l  = reinterpret_cast<const uint4*>(wrow_l)[tid & 3];

    for (int k0 = 0; k0 < C_N; k0 += 32) {
        __syncthreads();   // previous compute done before overwriting smem
        {
            uint32_t* d = &sAh[ar * PADW + awo];
            d[0] = pa_h0.x; d[1] = pa_h0.y; d[2] = pa_h0.z; d[3] = pa_h0.w;
            d[4] = pa_h1.x; d[5] = pa_h1.y; d[6] = pa_h1.z; d[7] = pa_h1.w;
            d = &sAl[ar * PADW + awo];
            d[0] = pa_l0.x; d[1] = pa_l0.y; d[2] = pa_l0.z; d[3] = pa_l0.w;
            d[4] = pa_l1.x; d[5] = pa_l1.y; d[6] = pa_l1.z; d[7] = pa_l1.w;
            d = &sWh[wr * PADW + wwo];
            d[0] = pw_h.x; d[1] = pw_h.y; d[2] = pw_h.z; d[3] = pw_h.w;
            d = &sWl[wr * PADW + wwo];
            d[0] = pw_l.x; d[1] = pw_l.y; d[2] = pw_l.z; d[3] = pw_l.w;
        }
        __syncthreads();

        if (k0 + 32 < C_N) {   // prefetch next tile (overlaps compute)
            const uint4* pah = reinterpret_cast<const uint4*>(arow_h + k0 + 32);
            const uint4* pal = reinterpret_cast<const uint4*>(arow_l + k0 + 32);
            pa_h0 = pah[(awo >> 2) + 0]; pa_h1 = pah[(awo >> 2) + 1];
            pa_l0 = pal[(awo >> 2) + 0]; pa_l1 = pal[(awo >> 2) + 1];
            pw_h = reinterpret_cast<const uint4*>(wrow_h + k0 + 32)[tid & 3];
            pw_l = reinterpret_cast<const uint4*>(wrow_l + k0 + 32)[tid & 3];
        }

#pragma unroll
        for (int s = 0; s < 2; ++s) {          // two k16 steps per BK=32
            const int ko = s * 8;
            uint32_t ah[2][4], al[2][4], bh[4][2], bl[4][2];
#pragma unroll
            for (int t = 0; t < 2; ++t) {
                int r0 = (mb + t * 16 + g) * PADW;
                int r1 = r0 + 8 * PADW;
                ah[t][0] = sAh[r0 + tig + ko];     ah[t][1] = sAh[r1 + tig + ko];
                ah[t][2] = sAh[r0 + tig + 4 + ko]; ah[t][3] = sAh[r1 + tig + 4 + ko];
                al[t][0] = sAl[r0 + tig + ko];     al[t][1] = sAl[r1 + tig + ko];
                al[t][2] = sAl[r0 + tig + 4 + ko]; al[t][3] = sAl[r1 + tig + 4 + ko];
            }
#pragma unroll
            for (int u = 0; u < 4; ++u) {
                int c0 = (nb + u * 8 + g) * PADW;
                bh[u][0] = sWh[c0 + tig + ko]; bh[u][1] = sWh[c0 + tig + 4 + ko];
                bl[u][0] = sWl[c0 + tig + ko]; bl[u][1] = sWl[c0 + tig + 4 + ko];
            }
#pragma unroll
            for (int t = 0; t < 2; ++t)
#pragma unroll
                for (int u = 0; u < 4; ++u) {
                    mma_bf16(acc[t][u], ah[t], bh[u]);   // hi*hi
                    mma_bf16(acc[t][u], ah[t], bl[u]);   // hi*lo
                    mma_bf16(acc[t][u], al[t], bh[u]);   // lo*hi
                }
        }
    }

    // ---- epilogue: bias + fp32 store ----
#pragma unroll
    for (int t = 0; t < 2; ++t) {
        int row0 = m0 + mb + t * 16 + g;
#pragma unroll
        for (int u = 0; u < 4; ++u) {
            int col = n0 + nb + u * 8 + 2 * tig;
            float2 bv = *reinterpret_cast<const float2*>(bias + col);
            float2 o0 = make_float2(acc[t][u][0] + bv.x, acc[t][u][1] + bv.y);
            float2 o1 = make_float2(acc[t][u][2] + bv.x, acc[t][u][3] + bv.y);
            *reinterpret_cast<float2*>(out + (size_t)row0 * ldo + col) = o0;
            *reinterpret_cast<float2*>(out + (size_t)(row0 + 8) * ldo + col) = o1;
        }
    }
}

// ---------------------------------------------------------------------------
// Kernel 3: fused leaf-block attention (fp32 math; bf16 split output).
//   One CTA per (b, block). 288 threads (9 warps).
// ---------------------------------------------------------------------------
struct SmemAtt {
    float4 ef[L_Q * KEY_N];     // 66560 B   (overridden bias vectors)
    float  m01[L_Q * KEY_N];    // 16640 B   (1.0 keep / 0.0 masked)
    float  qT[HD_N * 65];       // qT[d][i], stride 65
    float  kT[HD_N * 69];       // kT[d][j], stride 69
    float  v [KEY_N * 68];      // v[j][d],  stride 68
    float  s [L_Q * KEY_N];     // scores / combined
    float  egw[H_N][4];
    float  egb[H_N];
};

__global__ __launch_bounds__(288, 1)
void attn_kernel(const float* __restrict__ ef_g,
                 const int*   __restrict__ mask_g,
                 const float* __restrict__ egw_g,
                 const float* __restrict__ egb_g)
{
    extern __shared__ char smem_raw[];
    SmemAtt& sm = *reinterpret_cast<SmemAtt*>(smem_raw);

    const int bb  = blockIdx.x;      // 0..1023
    const int tid = threadIdx.x;     // 0..287
    const int NT  = 288;
    const float scale = 0.125f;      // HD^-0.5

    // ---- load edge_feats (+ overrides) and mask, once per CTA ----
    const float4* efg4 = reinterpret_cast<const float4*>(ef_g) + (size_t)bb * L_Q * KEY_N;
    const int*    mg   = mask_g + (size_t)bb * L_Q * KEY_N;
    for (int e = tid; e < L_Q * KEY_N; e += NT) {
        int i = e / KEY_N;
        int j = e - i * KEY_N;
        float4 t = efg4[e];
        if (j == L_Q || j == i) t = make_float4(0.f, 0.f, 0.f, 1.f);
        sm.ef[e]  = t;
        sm.m01[e] = (mg[e] != 0) ? 1.0f : 0.0f;
    }
    if (tid < H_N * 4) ((float*)sm.egw)[tid] = egw_g[tid];
    if (tid < H_N)     sm.egb[tid] = egb_g[tid];

    const int warp = tid >> 5;
    const int lane = tid & 31;

    for (int h = 0; h < H_N; ++h) {
        __syncthreads();   // covers initial loads (h=0) and s reuse (h>0)

        // ---- stage q, k, v head slices into smem ----
        const float* qh = g_q + ((size_t)bb * L_Q) * C_N + h * HD_N;
        for (int e = tid; e < L_Q * HD_N; e += NT) {
            int i = e >> 6, d = e & 63;
            sm.qT[d * 65 + i] = qh[(size_t)i * C_N + d];
        }
        const float* kh = g_kv + ((size_t)bb * KEY_N) * (2 * C_N) + h * HD_N;
        const float* vh = kh + C_N;
        for (int e = tid; e < KEY_N * HD_N; e += NT) {
            int j = e >> 6, d = e & 63;
            sm.kT[d * 69 + j] = kh[(size_t)j * (2 * C_N) + d];
            sm.v [j * 68 + d] = vh[(size_t)j * (2 * C_N) + d];
        }
        __syncthreads();

        // ---- scores = scale * q k^T + bias3, masked -> -1e30 ----
        if (tid < 272) {
            int tx = tid % 17, ty = tid / 17;
            int j0 = tx * 4,  i0 = ty * 4;
            float acc[4][4] = {};
            const float* qp = &sm.qT[i0];
            const float* kp = &sm.kT[j0];
#pragma unroll 4
            for (int d = 0; d < HD_N; ++d) {
                float a0 = qp[d*65+0], a1 = qp[d*65+1], a2 = qp[d*65+2], a3 = qp[d*65+3];
                float b0 = kp[d*69+0], b1 = kp[d*69+1], b2 = kp[d*69+2], b3 = kp[d*69+3];
                acc[0][0] += a0*b0; acc[0][1] += a0*b1; acc[0][2] += a0*b2; acc[0][3] += a0*b3;
                acc[1][0] += a1*b0; acc[1][1] += a1*b1; acc[1][2] += a1*b2; acc[1][3] += a1*b3;
                acc[2][0] += a2*b0; acc[2][1] += a2*b1; acc[2][2] += a2*b2; acc[2][3] += a2*b3;
                acc[3][0] += a3*b0; acc[3][1] += a3*b1; acc[3][2] += a3*b2; acc[3][3] += a3*b3;
            }
#pragma unroll
            for (int ii = 0; ii < 4; ++ii)
#pragma unroll
                for (int jj = 0; jj < 4; ++jj) {
                    int j = j0 + jj;
                    if (j < KEY_N) {
                        int e = (i0 + ii) * KEY_N + j;
                        sm.s[e] = (sm.m01[e] != 0.f)
                                ? acc[ii][jj] * scale + sm.ef[e].w
                                : -1e30f;
                    }
                }
        }
        __syncthreads();

        // ---- softmax over 65 keys + combine with lew ----
        {
            float w0 = sm.egw[h][0], w1 = sm.egw[h][1];
            float w2 = sm.egw[h][2], w3 = sm.egw[h][3];
            float bh = sm.egb[h];
            for (int i = warp; i < L_Q; i += 9) {
                int e0i = i * KEY_N + lane;
                int e1i = e0i + 32;
                int e2i = i * KEY_N + 64;
                float v0 = sm.s[e0i];
                float v1 = sm.s[e1i];
                float v2 = (lane == 0) ? sm.s[e2i] : -1e30f;
                float mx = fmaxf(fmaxf(v0, v1), v2);
#pragma unroll
                for (int off = 16; off; off >>= 1)
                    mx = fmaxf(mx, __shfl_xor_sync(0xffffffffu, mx, off));
                float p0 = __expf(v0 - mx);
                float p1 = __expf(v1 - mx);
                float p2 = (lane == 0) ? __expf(v2 - mx) : 0.f;
                float ssum = p0 + p1 + p2;
#pragma unroll
                for (int off = 16; off; off >>= 1)
                    ssum += __shfl_xor_sync(0xffffffffu, ssum, off);
                float inv = 1.0f / ssum;

                float4 b0 = sm.ef[e0i];
                float lew0 = b0.x*w0 + b0.y*w1 + b0.z*w2 + b0.w*w3 + bh;
                sm.s[e0i] = (sm.m01[e0i] != 0.f) ? (p0 * inv + lew0) : 0.f;

                float4 b1 = sm.ef[e1i];
                float lew1 = b1.x*w0 + b1.y*w1 + b1.z*w2 + b1.w*w3 + bh;
                sm.s[e1i] = (sm.m01[e1i] != 0.f) ? (p1 * inv + lew1) : 0.f;

                if (lane == 0) {
                    float4 b2 = sm.ef[e2i];
                    float lew2 = b2.x*w0 + b2.y*w1 + b2.z*w2 + b2.w*w3 + bh;
                    sm.s[e2i] = (sm.m01[e2i] != 0.f) ? (p2 * inv + lew2) : 0.f;
                }
            }
        }
        __syncthreads();

        // ---- out = combined(64x65) @ v(65x64), bf16 split store ----
        if (tid < 256) {
            int tx = tid & 15, ty = tid >> 4;
            int d0 = tx * 4, i0 = ty * 4;
            float acc[4][4] = {};
            for (int j = 0; j < KEY_N; ++j) {
                float4 bv = *(const float4*)&sm.v[j * 68 + d0];
                float a0 = sm.s[(i0 + 0) * KEY_N + j];
                float a1 = sm.s[(i0 + 1) * KEY_N + j];
                float a2 = sm.s[(i0 + 2) * KEY_N + j];
                float a3 = sm.s[(i0 + 3) * KEY_N + j];
                acc[0][0] += a0*bv.x; acc[0][1] += a0*bv.y; acc[0][2] += a0*bv.z; acc[0][3] += a0*bv.w;
                acc[1][0] += a1*bv.x; acc[1][1] += a1*bv.y; acc[1][2] += a1*bv.z; acc[1][3] += a1*bv.w;
                acc[2][0] += a2*bv.x; acc[2][1] += a2*bv.y; acc[2][2] += a2*bv.z; acc[2][3] += a2*bv.w;
                acc[3][0] += a3*bv.x; acc[3][1] += a3*bv.y; acc[3][2] += a3*bv.z; acc[3][3] += a3*bv.w;
            }
#pragma unroll
            for (int ii = 0; ii < 4; ++ii) {
                size_t off = ((size_t)bb * L_Q + i0 + ii) * C_N + h * HD_N + d0;
                __nv_bfloat16 h0, h1, h2, h3, l0, l1, l2, l3;
                split2(acc[ii][0], h0, l0); split2(acc[ii][1], h1, l1);
                split2(acc[ii][2], h2, l2); split2(acc[ii][3], h3, l3);
                __nv_bfloat162 ha; ha.x = h0; ha.y = h1;
                __nv_bfloat162 hb; hb.x = h2; hb.y = h3;
                __nv_bfloat162 la; la.x = l0; la.y = l1;
                __nv_bfloat162 lb; lb.x = l2; lb.y = l3;
                __nv_bfloat162* ph = reinterpret_cast<__nv_bfloat162*>(g_ath + off);
                __nv_bfloat162* pl = reinterpret_cast<__nv_bfloat162*>(g_atl + off);
                ph[0] = ha; ph[1] = hb;
                pl[0] = la; pl[1] = lb;
            }
        }
    }
}

// ---------------------------------------------------------------------------
// Launch
// ---------------------------------------------------------------------------
extern "C" void kernel_launch(void* const* d_in, const int* in_sizes, int n_in,
                              void* d_out, int out_size)
{
    (void)in_sizes; (void)n_in; (void)out_size;
    const float* x          = (const float*)d_in[0];
    const int*   attn_mask  = (const int*)  d_in[1];
    const float* edge_feats = (const float*)d_in[2];
    const float* qkv_w      = (const float*)d_in[3];
    const float* qkv_b      = (const float*)d_in[4];
    const float* proj_w     = (const float*)d_in[5];
    const float* proj_b     = (const float*)d_in[6];
    const float* eg_w       = (const float*)d_in[7];
    const float* eg_b       = (const float*)d_in[8];
    float* out = (float*)d_out;

    __nv_bfloat16 *xh, *xl, *wqh, *wql, *wph, *wpl, *ath, *atl;
    float *qp, *kvp;
    cudaGetSymbolAddress((void**)&xh,  g_xh);
    cudaGetSymbolAddress((void**)&xl,  g_xl);
    cudaGetSymbolAddress((void**)&wqh, g_wqkvh);
    cudaGetSymbolAddress((void**)&wql, g_wqkvl);
    cudaGetSymbolAddress((void**)&wph, g_wph);
    cudaGetSymbolAddress((void**)&wpl, g_wpl);
    cudaGetSymbolAddress((void**)&ath, g_ath);
    cudaGetSymbolAddress((void**)&atl, g_atl);
    cudaGetSymbolAddress((void**)&qp,  g_q);
    cudaGetSymbolAddress((void**)&kvp, g_kv);

    const int smem_att = (int)sizeof(SmemAtt);
    cudaFuncSetAttribute(attn_kernel,
                         cudaFuncAttributeMaxDynamicSharedMemorySize, smem_att);

    // 0) bf16 hi/lo splits of x and weights
    split_kernel<<<(MQ_N * C_N / 4 + 255) / 256, 256>>>(x, xh, xl, MQ_N * C_N / 4);
    split_kernel<<<(3 * C_N * C_N / 4 + 255) / 256, 256>>>(qkv_w, wqh, wql, 3 * C_N * C_N / 4);
    split_kernel<<<(C_N * C_N / 4 + 255) / 256, 256>>>(proj_w, wph, wpl, C_N * C_N / 4);

    // 1) block means (bf16 split)
    mean_kernel<<<NB_N, C_N>>>(x);

    // 2) q = x @ Wq^T + bq
    gemm_bf16<<<dim3(MQ_N / 128, C_N / 64), 256>>>(
        xh, xl, wqh, wql, qkv_b, qp, C_N, 0);

    // 3) [k|v] = concat(x, mean) @ [Wk;Wv]^T + [bk;bv]  (virtual concat)
    gemm_bf16<<<dim3(MKV_N / 128, (2 * C_N) / 64), 256>>>(
        xh, xl, wqh + C_N * C_N, wql + C_N * C_N, qkv_b + C_N, kvp, 2 * C_N, 1);

    // 4) fused attention (scores + bias + mask + softmax + lew + AV)
    attn_kernel<<<NB_N, 288, smem_att>>>(edge_feats, attn_mask, eg_w, eg_b);

    // 5) out = attn @ Wp^T + bp
    gemm_bf16<<<dim3(MQ_N / 128, C_N / 64), 256>>>(
        ath, atl, wph, wpl, proj_b, out, C_N, 0);
}

// round 10
// speedup vs baseline: 1.2305x; 1.2305x over previous
#include <cuda_runtime.h>
#include <cuda_bf16.h>
#include <cstdint>

// ---------------------------------------------------------------------------
// Problem constants
// ---------------------------------------------------------------------------
#define L_Q   64
#define KEY_N 65
#define H_N   8
#define HD_N  64
#define C_N   512
#define NB_N  1024              // B * nb = 2 * 512
#define MQ_N  (NB_N * L_Q)      // 65536 rows of x / q / attn-out
#define MKV_N (NB_N * KEY_N)    // 66560 rows of kv (= 520 * 128)

// ---------------------------------------------------------------------------
// Device scratch (no cudaMalloc allowed)
// ---------------------------------------------------------------------------
__device__ __nv_bfloat16 g_xh[MQ_N * C_N];
__device__ __nv_bfloat16 g_xl[MQ_N * C_N];
__device__ __nv_bfloat16 g_bmh[NB_N * C_N];
__device__ __nv_bfloat16 g_bml[NB_N * C_N];
__device__ __nv_bfloat16 g_wqkvh[3 * C_N * C_N];
__device__ __nv_bfloat16 g_wqkvl[3 * C_N * C_N];
__device__ __nv_bfloat16 g_wph[C_N * C_N];
__device__ __nv_bfloat16 g_wpl[C_N * C_N];
__device__ __nv_bfloat16 g_ath[MQ_N * C_N];
__device__ __nv_bfloat16 g_atl[MQ_N * C_N];
__device__ float g_q[MQ_N * C_N];
__device__ float g_kv[MKV_N * 2 * C_N];

// ---------------------------------------------------------------------------
// PTX helpers (mma.sync / ldmatrix / cp.async — all plain sm_103 features)
// ---------------------------------------------------------------------------
__device__ __forceinline__ uint32_t smem_u32(const void* p)
{
    uint32_t a;
    asm("{ .reg .u64 t; cvta.to.shared.u64 t, %1; cvt.u32.u64 %0, t; }"
        : "=r"(a) : "l"(p));
    return a;
}

__device__ __forceinline__ void mma_bf16(float* c, const uint32_t* a, const uint32_t* b)
{
    asm volatile(
        "mma.sync.aligned.m16n8k16.row.col.f32.bf16.bf16.f32 "
        "{%0,%1,%2,%3}, {%4,%5,%6,%7}, {%8,%9}, {%0,%1,%2,%3};\n"
        : "+f"(c[0]), "+f"(c[1]), "+f"(c[2]), "+f"(c[3])
        : "r"(a[0]), "r"(a[1]), "r"(a[2]), "r"(a[3]),
          "r"(b[0]), "r"(b[1]));
}

#define LDSM_X4(r, a) \
    asm volatile("ldmatrix.sync.aligned.m8n8.x4.shared.b16 {%0,%1,%2,%3}, [%4];" \
        : "=r"((r)[0]), "=r"((r)[1]), "=r"((r)[2]), "=r"((r)[3]) : "r"(a))

#define CPA16(dst, src) \
    asm volatile("cp.async.cg.shared.global [%0], [%1], 16;" \
                 :: "r"(dst), "l"(src) : "memory")
#define CPA_COMMIT() asm volatile("cp.async.commit_group;" ::: "memory")
template <int N>
__device__ __forceinline__ void cpa_wait()
{
    asm volatile("cp.async.wait_group %0;" :: "n"(N) : "memory");
}

// ---------------------------------------------------------------------------
// Helpers
// ---------------------------------------------------------------------------
__device__ __forceinline__ void split2(float f, __nv_bfloat16& h, __nv_bfloat16& l)
{
    h = __float2bfloat16(f);
    l = __float2bfloat16(f - __bfloat162float(h));
}

// ---------------------------------------------------------------------------
// Kernel 0: fp32 -> bf16 hi/lo split
// ---------------------------------------------------------------------------
__global__ void split_kernel(const float* __restrict__ src,
                             __nv_bfloat16* __restrict__ hi,
                             __nv_bfloat16* __restrict__ lo, int n4)
{
    int i = blockIdx.x * 256 + threadIdx.x;
    if (i >= n4) return;
    float4 f = reinterpret_cast<const float4*>(src)[i];
    __nv_bfloat16 h0, h1, h2, h3, l0, l1, l2, l3;
    split2(f.x, h0, l0); split2(f.y, h1, l1);
    split2(f.z, h2, l2); split2(f.w, h3, l3);
    __nv_bfloat162 ha; ha.x = h0; ha.y = h1;
    __nv_bfloat162 hb; hb.x = h2; hb.y = h3;
    __nv_bfloat162 la; la.x = l0; la.y = l1;
    __nv_bfloat162 lb; lb.x = l2; lb.y = l3;
    __nv_bfloat162* hp = reinterpret_cast<__nv_bfloat162*>(hi) + (size_t)i * 2;
    __nv_bfloat162* lp = reinterpret_cast<__nv_bfloat162*>(lo) + (size_t)i * 2;
    hp[0] = ha; hp[1] = hb;
    lp[0] = la; lp[1] = lb;
}

// ---------------------------------------------------------------------------
// Kernel 1: per-block mean of x -> bf16 hi/lo
// ---------------------------------------------------------------------------
__global__ void mean_kernel(const float* __restrict__ x)
{
    int bb = blockIdx.x;
    int c  = threadIdx.x;
    const float* xp = x + ((size_t)bb * L_Q) * C_N + c;
    float s = 0.f;
#pragma unroll 8
    for (int l = 0; l < L_Q; ++l) s += xp[(size_t)l * C_N];
    s *= (1.0f / 64.0f);
    __nv_bfloat16 h, l;
    split2(s, h, l);
    g_bmh[bb * C_N + c] = h;
    g_bml[bb * C_N + c] = l;
}

// ---------------------------------------------------------------------------
// Kernel 2: HMMA bf16 split GEMM   out[M,N] = A[M,512] @ W[N,512]^T + bias
//   CTA 128x128, BK=32, 256 thr (8 warps, 2x4), warp tile 64x32.
//   ldmatrix.x4 fragment loads from 80B-pitch smem (conflict-free),
//   cp.async 2-stage pipeline. 3 products AhWh+AhWl+AlWh, fp32 acc.
//   kvmode=1: logical A row r -> bb=r/65, l=r%65; l<64 -> x row, l==64 -> mean.
//   Grid: x = N tile, y = M tile (A reuse across N within a wave).
// ---------------------------------------------------------------------------
#define ROWB   80                 // bytes per smem row (32 bf16 used + pad)
#define TILE_B (128 * ROWB)       // 10240 B per tensor tile
#define T_AH   0
#define T_AL   (1 * TILE_B)
#define T_BH   (2 * TILE_B)
#define T_BL   (3 * TILE_B)
#define STAGE  (4 * TILE_B)       // 40960 B
#define GE_SMEM (2 * STAGE)       // 81920 B

__global__ __launch_bounds__(256, 1)
void gemm_hmma(const __nv_bfloat16* __restrict__ Ah,
               const __nv_bfloat16* __restrict__ Al,
               const __nv_bfloat16* __restrict__ Wh,
               const __nv_bfloat16* __restrict__ Wl,
               const float* __restrict__ bias,
               float* __restrict__ out,
               int ldo, int kvmode)
{
    extern __shared__ __align__(16) char smem[];
    const uint32_t sb = smem_u32(smem);
    const int tid  = threadIdx.x;
    const int n0 = blockIdx.x * 128;
    const int m0 = blockIdx.y * 128;
    const int warp = tid >> 5, lane = tid & 31;
    const int wm0 = (warp >> 2) * 64;     // warp M offset (0/64)
    const int wn0 = (warp & 3) * 32;      // warp N offset (0/32/64/96)

    // ---- global->smem mapping: 2 rows per thread per tensor ----
    const int r0  = tid >> 2;             // 0..63
    const int seg = tid & 3;              // 16B segment within 64B row
    const uint32_t dA0 = (uint32_t)(r0 * ROWB + seg * 16);
    const uint32_t dA1 = dA0 + 64 * ROWB;

    const __nv_bfloat16 *aH0, *aL0, *aH1, *aL1;
    {
        int rr[2] = { r0, r0 + 64 };
        const __nv_bfloat16* ph[2];
        const __nv_bfloat16* pl[2];
#pragma unroll
        for (int j = 0; j < 2; ++j) {
            int gr = m0 + rr[j];
            if (!kvmode) {
                ph[j] = Ah + (size_t)gr * C_N;
                pl[j] = Al + (size_t)gr * C_N;
            } else {
                int bb = gr / KEY_N;
                int l  = gr - bb * KEY_N;
                if (l < L_Q) {
                    ph[j] = Ah + (size_t)(bb * L_Q + l) * C_N;
                    pl[j] = Al + (size_t)(bb * L_Q + l) * C_N;
                } else {
                    ph[j] = g_bmh + (size_t)bb * C_N;
                    pl[j] = g_bml + (size_t)bb * C_N;
                }
            }
            ph[j] += seg * 8;
            pl[j] += seg * 8;
        }
        aH0 = ph[0]; aL0 = pl[0]; aH1 = ph[1]; aL1 = pl[1];
    }
    const __nv_bfloat16* bH0 = Wh + (size_t)(n0 + r0) * C_N + seg * 8;
    const __nv_bfloat16* bL0 = Wl + (size_t)(n0 + r0) * C_N + seg * 8;
    const __nv_bfloat16* bH1 = Wh + (size_t)(n0 + r0 + 64) * C_N + seg * 8;
    const __nv_bfloat16* bL1 = Wl + (size_t)(n0 + r0 + 64) * C_N + seg * 8;

    auto load_stage = [&](int it) {
        const uint32_t base = sb + (uint32_t)(it & 1) * STAGE;
        const int k0 = it * 32;
        CPA16(base + T_AH + dA0, aH0 + k0);
        CPA16(base + T_AH + dA1, aH1 + k0);
        CPA16(base + T_AL + dA0, aL0 + k0);
        CPA16(base + T_AL + dA1, aL1 + k0);
        CPA16(base + T_BH + dA0, bH0 + k0);
        CPA16(base + T_BH + dA1, bH1 + k0);
        CPA16(base + T_BL + dA0, bL0 + k0);
        CPA16(base + T_BL + dA1, bL1 + k0);
        CPA_COMMIT();
    };

    float acc[4][4][4] = {};

    load_stage(0);
    load_stage(1);

    // ldmatrix per-lane address components
    const int lrow = lane & 15;
    const int lk8  = (lane >> 4) * 8;     // element offset 0 or 8

    for (int it = 0; it < 16; ++it) {
        if (it < 15) cpa_wait<1>(); else cpa_wait<0>();
        __syncthreads();                  // stage (it&1) fully resident
        const uint32_t base = sb + (uint32_t)(it & 1) * STAGE;
#pragma unroll
        for (int ks = 0; ks < 2; ++ks) {
            const int kofs = ks * 16;
            uint32_t ah[4][4], al[4][4];
#pragma unroll
            for (int tm = 0; tm < 4; ++tm) {
                uint32_t off = (uint32_t)((wm0 + tm * 16 + lrow) * ROWB
                                          + (kofs + lk8) * 2);
                LDSM_X4(ah[tm], base + T_AH + off);
                LDSM_X4(al[tm], base + T_AL + off);
            }
            uint32_t bh[2][4], bl[2][4];
#pragma unroll
            for (int tb = 0; tb < 2; ++tb) {
                uint32_t off = (uint32_t)((wn0 + tb * 16 + lrow) * ROWB
                                          + (kofs + lk8) * 2);
                LDSM_X4(bh[tb], base + T_BH + off);
                LDSM_X4(bl[tb], base + T_BL + off);
            }
#pragma unroll
            for (int tm = 0; tm < 4; ++tm)
#pragma unroll
                for (int tn = 0; tn < 4; ++tn) {
                    // n8 tile tn: ldmatrix group tn>>1, sub-tile tn&1
                    uint32_t bfh[2] = { bh[tn >> 1][tn & 1], bh[tn >> 1][(tn & 1) + 2] };
                    uint32_t bfl[2] = { bl[tn >> 1][tn & 1], bl[tn >> 1][(tn & 1) + 2] };
                    mma_bf16(acc[tm][tn], ah[tm], bfh);   // hi*hi
                    mma_bf16(acc[tm][tn], ah[tm], bfl);   // hi*lo
                    mma_bf16(acc[tm][tn], al[tm], bfh);   // lo*hi
                }
        }
        __syncthreads();                  // all warps done reading stage
        if (it + 2 < 16) load_stage(it + 2);
    }

    // ---- epilogue: bias + fp32 store (mma C layout) ----
    const int qr = lane >> 2;             // row within 8
    const int qc = (lane & 3) * 2;        // col pair
#pragma unroll
    for (int tm = 0; tm < 4; ++tm) {
        int row = m0 + wm0 + tm * 16 + qr;
#pragma unroll
        for (int tn = 0; tn < 4; ++tn) {
            int col = n0 + wn0 + tn * 8 + qc;
            float2 bv = *reinterpret_cast<const float2*>(bias + col);
            float2 o0 = make_float2(acc[tm][tn][0] + bv.x, acc[tm][tn][1] + bv.y);
            float2 o1 = make_float2(acc[tm][tn][2] + bv.x, acc[tm][tn][3] + bv.y);
            *reinterpret_cast<float2*>(out + (size_t)row * ldo + col) = o0;
            *reinterpret_cast<float2*>(out + (size_t)(row + 8) * ldo + col) = o1;
        }
    }
}

// ---------------------------------------------------------------------------
// Kernel 3: fused leaf-block attention (fp32; bf16-split output for proj)
// ---------------------------------------------------------------------------
struct SmemAtt {
    float4 ef[L_Q * KEY_N];
    float  m01[L_Q * KEY_N];
    float  qT[HD_N * 65];
    float  kT[HD_N * 69];
    float  v [KEY_N * 68];
    float  s [L_Q * KEY_N];
    float  egw[H_N][4];
    float  egb[H_N];
};

__global__ __launch_bounds__(288, 1)
void attn_kernel(const float* __restrict__ ef_g,
                 const int*   __restrict__ mask_g,
                 const float* __restrict__ egw_g,
                 const float* __restrict__ egb_g)
{
    extern __shared__ char smem_raw[];
    SmemAtt& sm = *reinterpret_cast<SmemAtt*>(smem_raw);

    const int bb  = blockIdx.x;
    const int tid = threadIdx.x;
    const int NT  = 288;
    const float scale = 0.125f;

    const float4* efg4 = reinterpret_cast<const float4*>(ef_g) + (size_t)bb * L_Q * KEY_N;
    const int*    mg   = mask_g + (size_t)bb * L_Q * KEY_N;
    for (int e = tid; e < L_Q * KEY_N; e += NT) {
        int i = e / KEY_N;
        int j = e - i * KEY_N;
        float4 t = efg4[e];
        if (j == L_Q || j == i) t = make_float4(0.f, 0.f, 0.f, 1.f);
        sm.ef[e]  = t;
        sm.m01[e] = (mg[e] != 0) ? 1.0f : 0.0f;
    }
    if (tid < H_N * 4) ((float*)sm.egw)[tid] = egw_g[tid];
    if (tid < H_N)     sm.egb[tid] = egb_g[tid];

    const int warp = tid >> 5;
    const int lane = tid & 31;

    for (int h = 0; h < H_N; ++h) {
        __syncthreads();

        const float* qh = g_q + ((size_t)bb * L_Q) * C_N + h * HD_N;
        for (int e = tid; e < L_Q * HD_N; e += NT) {
            int i = e >> 6, d = e & 63;
            sm.qT[d * 65 + i] = qh[(size_t)i * C_N + d];
        }
        const float* kh = g_kv + ((size_t)bb * KEY_N) * (2 * C_N) + h * HD_N;
        const float* vh = kh + C_N;
        for (int e = tid; e < KEY_N * HD_N; e += NT) {
            int j = e >> 6, d = e & 63;
            sm.kT[d * 69 + j] = kh[(size_t)j * (2 * C_N) + d];
            sm.v [j * 68 + d] = vh[(size_t)j * (2 * C_N) + d];
        }
        __syncthreads();

        if (tid < 272) {
            int tx = tid % 17, ty = tid / 17;
            int j0 = tx * 4,  i0 = ty * 4;
            float acc[4][4] = {};
            const float* qp = &sm.qT[i0];
            const float* kp = &sm.kT[j0];
#pragma unroll 4
            for (int d = 0; d < HD_N; ++d) {
                float a0 = qp[d*65+0], a1 = qp[d*65+1], a2 = qp[d*65+2], a3 = qp[d*65+3];
                float b0 = kp[d*69+0], b1 = kp[d*69+1], b2 = kp[d*69+2], b3 = kp[d*69+3];
                acc[0][0] += a0*b0; acc[0][1] += a0*b1; acc[0][2] += a0*b2; acc[0][3] += a0*b3;
                acc[1][0] += a1*b0; acc[1][1] += a1*b1; acc[1][2] += a1*b2; acc[1][3] += a1*b3;
                acc[2][0] += a2*b0; acc[2][1] += a2*b1; acc[2][2] += a2*b2; acc[2][3] += a2*b3;
                acc[3][0] += a3*b0; acc[3][1] += a3*b1; acc[3][2] += a3*b2; acc[3][3] += a3*b3;
            }
#pragma unroll
            for (int ii = 0; ii < 4; ++ii)
#pragma unroll
                for (int jj = 0; jj < 4; ++jj) {
                    int j = j0 + jj;
                    if (j < KEY_N) {
                        int e = (i0 + ii) * KEY_N + j;
                        sm.s[e] = (sm.m01[e] != 0.f)
                                ? acc[ii][jj] * scale + sm.ef[e].w
                                : -1e30f;
                    }
                }
        }
        __syncthreads();

        {
            float w0 = sm.egw[h][0], w1 = sm.egw[h][1];
            float w2 = sm.egw[h][2], w3 = sm.egw[h][3];
            float bh = sm.egb[h];
            for (int i = warp; i < L_Q; i += 9) {
                int e0i = i * KEY_N + lane;
                int e1i = e0i + 32;
                int e2i = i * KEY_N + 64;
                float v0 = sm.s[e0i];
                float v1 = sm.s[e1i];
                float v2 = (lane == 0) ? sm.s[e2i] : -1e30f;
                float mx = fmaxf(fmaxf(v0, v1), v2);
#pragma unroll
                for (int off = 16; off; off >>= 1)
                    mx = fmaxf(mx, __shfl_xor_sync(0xffffffffu, mx, off));
                float p0 = __expf(v0 - mx);
                float p1 = __expf(v1 - mx);
                float p2 = (lane == 0) ? __expf(v2 - mx) : 0.f;
                float ssum = p0 + p1 + p2;
#pragma unroll
                for (int off = 16; off; off >>= 1)
                    ssum += __shfl_xor_sync(0xffffffffu, ssum, off);
                float inv = 1.0f / ssum;

                float4 b0 = sm.ef[e0i];
                float lew0 = b0.x*w0 + b0.y*w1 + b0.z*w2 + b0.w*w3 + bh;
                sm.s[e0i] = (sm.m01[e0i] != 0.f) ? (p0 * inv + lew0) : 0.f;

                float4 b1 = sm.ef[e1i];
                float lew1 = b1.x*w0 + b1.y*w1 + b1.z*w2 + b1.w*w3 + bh;
                sm.s[e1i] = (sm.m01[e1i] != 0.f) ? (p1 * inv + lew1) : 0.f;

                if (lane == 0) {
                    float4 b2 = sm.ef[e2i];
                    float lew2 = b2.x*w0 + b2.y*w1 + b2.z*w2 + b2.w*w3 + bh;
                    sm.s[e2i] = (sm.m01[e2i] != 0.f) ? (p2 * inv + lew2) : 0.f;
                }
            }
        }
        __syncthreads();

        if (tid < 256) {
            int tx = tid & 15, ty = tid >> 4;
            int d0 = tx * 4, i0 = ty * 4;
            float acc[4][4] = {};
            for (int j = 0; j < KEY_N; ++j) {
                float4 bv = *(const float4*)&sm.v[j * 68 + d0];
                float a0 = sm.s[(i0 + 0) * KEY_N + j];
                float a1 = sm.s[(i0 + 1) * KEY_N + j];
                float a2 = sm.s[(i0 + 2) * KEY_N + j];
                float a3 = sm.s[(i0 + 3) * KEY_N + j];
                acc[0][0] += a0*bv.x; acc[0][1] += a0*bv.y; acc[0][2] += a0*bv.z; acc[0][3] += a0*bv.w;
                acc[1][0] += a1*bv.x; acc[1][1] += a1*bv.y; acc[1][2] += a1*bv.z; acc[1][3] += a1*bv.w;
                acc[2][0] += a2*bv.x; acc[2][1] += a2*bv.y; acc[2][2] += a2*bv.z; acc[2][3] += a2*bv.w;
                acc[3][0] += a3*bv.x; acc[3][1] += a3*bv.y; acc[3][2] += a3*bv.z; acc[3][3] += a3*bv.w;
            }
#pragma unroll
            for (int ii = 0; ii < 4; ++ii) {
                size_t off = ((size_t)bb * L_Q + i0 + ii) * C_N + h * HD_N + d0;
                __nv_bfloat16 h0, h1, h2, h3, l0, l1, l2, l3;
                split2(acc[ii][0], h0, l0); split2(acc[ii][1], h1, l1);
                split2(acc[ii][2], h2, l2); split2(acc[ii][3], h3, l3);
                __nv_bfloat162 ha; ha.x = h0; ha.y = h1;
                __nv_bfloat162 hb; hb.x = h2; hb.y = h3;
                __nv_bfloat162 la; la.x = l0; la.y = l1;
                __nv_bfloat162 lb; lb.x = l2; lb.y = l3;
                __nv_bfloat162* ph = reinterpret_cast<__nv_bfloat162*>(g_ath + off);
                __nv_bfloat162* pl = reinterpret_cast<__nv_bfloat162*>(g_atl + off);
                ph[0] = ha; ph[1] = hb;
                pl[0] = la; pl[1] = lb;
            }
        }
    }
}

// ---------------------------------------------------------------------------
// Launch
// ---------------------------------------------------------------------------
extern "C" void kernel_launch(void* const* d_in, const int* in_sizes, int n_in,
                              void* d_out, int out_size)
{
    (void)in_sizes; (void)n_in; (void)out_size;
    const float* x          = (const float*)d_in[0];
    const int*   attn_mask  = (const int*)  d_in[1];
    const float* edge_feats = (const float*)d_in[2];
    const float* qkv_w      = (const float*)d_in[3];
    const float* qkv_b      = (const float*)d_in[4];
    const float* proj_w     = (const float*)d_in[5];
    const float* proj_b     = (const float*)d_in[6];
    const float* eg_w       = (const float*)d_in[7];
    const float* eg_b       = (const float*)d_in[8];
    float* out = (float*)d_out;

    __nv_bfloat16 *xh, *xl, *wqh, *wql, *wph, *wpl, *ath, *atl;
    float *qp, *kvp;
    cudaGetSymbolAddress((void**)&xh,  g_xh);
    cudaGetSymbolAddress((void**)&xl,  g_xl);
    cudaGetSymbolAddress((void**)&wqh, g_wqkvh);
    cudaGetSymbolAddress((void**)&wql, g_wqkvl);
    cudaGetSymbolAddress((void**)&wph, g_wph);
    cudaGetSymbolAddress((void**)&wpl, g_wpl);
    cudaGetSymbolAddress((void**)&ath, g_ath);
    cudaGetSymbolAddress((void**)&atl, g_atl);
    cudaGetSymbolAddress((void**)&qp,  g_q);
    cudaGetSymbolAddress((void**)&kvp, g_kv);

    const int smem_att = (int)sizeof(SmemAtt);
    cudaFuncSetAttribute(attn_kernel,
                         cudaFuncAttributeMaxDynamicSharedMemorySize, smem_att);
    cudaFuncSetAttribute(gemm_hmma,
                         cudaFuncAttributeMaxDynamicSharedMemorySize, GE_SMEM);

    // 0) bf16 hi/lo splits
    split_kernel<<<(MQ_N * C_N / 4 + 255) / 256, 256>>>(x, xh, xl, MQ_N * C_N / 4);
    split_kernel<<<(3 * C_N * C_N / 4 + 255) / 256, 256>>>(qkv_w, wqh, wql, 3 * C_N * C_N / 4);
    split_kernel<<<(C_N * C_N / 4 + 255) / 256, 256>>>(proj_w, wph, wpl, C_N * C_N / 4);

    // 1) block means (bf16 split)
    mean_kernel<<<NB_N, C_N>>>(x);

    // 2) q = x @ Wq^T + bq
    gemm_hmma<<<dim3(C_N / 128, MQ_N / 128), 256, GE_SMEM>>>(
        xh, xl, wqh, wql, qkv_b, qp, C_N, 0);

    // 3) [k|v] = concat(x, mean) @ [Wk;Wv]^T + [bk;bv]  (virtual concat)
    gemm_hmma<<<dim3((2 * C_N) / 128, MKV_N / 128), 256, GE_SMEM>>>(
        xh, xl, wqh + C_N * C_N, wql + C_N * C_N, qkv_b + C_N, kvp, 2 * C_N, 1);

    // 4) fused attention
    attn_kernel<<<NB_N, 288, smem_att>>>(edge_feats, attn_mask, eg_w, eg_b);

    // 5) out = attn @ Wp^T + bp
    gemm_hmma<<<dim3(C_N / 128, MQ_N / 128), 256, GE_SMEM>>>(
        ath, atl, wph, wpl, proj_b, out, C_N, 0);
}